// round 15
// baseline (speedup 1.0000x reference)
#include <cuda_runtime.h>

static constexpr int DIM    = 4096;
static constexpr int TOTAL  = 16384;
static constexpr int WIDTH  = 4;
static constexpr int BATCH  = 8;
static constexpr int NSLOTS = 256;
static constexpr int SLEN   = WIDTH - 1;        // 3
static constexpr int TPB    = 256;
static constexpr int VEC    = 4;                // float4s per thread
static constexpr int TCHUNK = TPB * 4 * VEC;    // 4096 t per block

static constexpr int NBLK_CS   = NSLOTS * DIM * SLEN / 4 / TPB;  // 3072
static constexpr int NBLK_CONV = (TOTAL / TCHUNK) * DIM;         // 16384
static constexpr int CHUNKS    = TOTAL / TCHUNK;                 // 4

// ---------------------------------------------------------------------------
// Fused kernel. blockIdx.x < NBLK_CS  -> conv_state copy/update part
//               blockIdx.x >= NBLK_CS -> main conv part (SMEM-free, shuffle halo)
// ---------------------------------------------------------------------------
__global__ __launch_bounds__(TPB) void fused_kernel(
    const float* __restrict__ x, const float* __restrict__ w,
    const float* __restrict__ cs, const int* __restrict__ qsl,
    const int* __restrict__ cidx, const int* __restrict__ imode,
    const int* __restrict__ ppad, const int* __restrict__ pres,
    float* __restrict__ out, float* __restrict__ out_cs)
{
    const int tid = threadIdx.x;

    if (blockIdx.x < NBLK_CS) {
        // ------------------- conv_state copy + update part -------------------
        __shared__ int sqsl[BATCH + 1];
        __shared__ int scidx[BATCH];
        __shared__ int simode[BATCH];

        if (tid < BATCH + 1) sqsl[tid] = qsl[tid];
        if (tid >= 32 && tid < 32 + BATCH) {
            scidx[tid - 32]  = cidx[tid - 32];
            simode[tid - 32] = imode[tid - 32];
        }
        __syncthreads();

        constexpr int PER_SLOT = DIM * SLEN;            // 12288 floats
        const int i4   = blockIdx.x * TPB + tid;        // float4 index
        const int f    = i4 * 4;                        // float index
        const int slot = f / PER_SLOT;
        const int pad  = *ppad;

        int b = -1;
        #pragma unroll
        for (int s = 0; s < BATCH; s++)
            if (scidx[s] == slot && scidx[s] != pad) b = s;

        const float4* in4  = reinterpret_cast<const float4*>(cs);
        float4*       out4 = reinterpret_cast<float4*>(out_cs);

        if (b < 0) {
            out4[i4] = in4[i4];
        } else {
            const int  end   = sqsl[b + 1];
            const int  L     = end - sqsl[b];
            const bool binit = (simode[b] != 0);
            const int  e0    = f - slot * PER_SLOT;     // element within slot

            float tmp[4];
            #pragma unroll
            for (int r = 0; r < 4; r++) {
                const int e  = e0 + r;
                const int dd = e / SLEN;
                const int j  = e - dd * SLEN;
                float v;
                if (L + j >= SLEN) v = x[(size_t)dd * TOTAL + (end - SLEN + j)];
                else               v = binit ? cs[(size_t)slot * PER_SLOT + dd * SLEN + (L + j)] : 0.f;
                tmp[r] = v;
            }
            out4[i4] = make_float4(tmp[0], tmp[1], tmp[2], tmp[3]);
        }
        return;
    }

    // --------------------------- main conv part ---------------------------
    const int cbid = blockIdx.x - NBLK_CS;
    const int d    = cbid / CHUNKS;
    const int t0   = (cbid % CHUNKS) * TCHUNK;
    const int lane = tid & 31;

    const float4* x4row = reinterpret_cast<const float4*>(x + (size_t)d * TOTAL);

    // issue the big streaming loads first (MLP=4)
    float4 xr[VEC];
    #pragma unroll
    for (int j = 0; j < VEC; j++)
        xr[j] = __ldcs(&x4row[t0 / 4 + j * TPB + tid]);

    // uniform metadata (broadcast loads)
    int qs[BATCH];
    #pragma unroll
    for (int s = 1; s < BATCH; s++) qs[s] = __ldg(&qsl[s]);
    const int    pad = __ldg(ppad);
    const float4 wv  = __ldg(&reinterpret_cast<const float4*>(w)[d]);
    const float  w3  = wv.w + (__ldg(pres) ? 1.0f : 0.0f);  // residual folded

    float4* out4row = reinterpret_cast<float4*>(out + (size_t)d * TOTAL);

    #pragma unroll
    for (int j = 0; j < VEC; j++) {
        const int ti    = j * TPB + tid;     // float4 index within chunk
        const int tbase = t0 + ti * 4;
        const float4 xv = xr[j];

        // halo: previous float4's .y .z .w come from lane-1 via shuffle;
        // warp-leading lane fetches from global (L2-hit, 1/32 of accesses)
        float py = __shfl_up_sync(0xffffffffu, xv.y, 1);
        float pz = __shfl_up_sync(0xffffffffu, xv.z, 1);
        float pw = __shfl_up_sync(0xffffffffu, xv.w, 1);
        if (lane == 0) {
            const int g = t0 / 4 + j * TPB + tid;
            float4 h = make_float4(0.f, 0.f, 0.f, 0.f);
            if (g > 0) h = __ldg(&x4row[g - 1]);
            py = h.y; pz = h.z; pw = h.w;
        }

        // fast ⟺ tbase>=3 and no boundary qsl[s] in [tbase-2, tbase+3]
        bool fast = (tbase >= 3);
        #pragma unroll
        for (int s = 1; s < BATCH; s++)
            fast = fast && ((unsigned)(qs[s] - (tbase - 2)) > 5u);

        float4 o;
        if (fast) {
            o.x = wv.x * py   + wv.y * pz   + wv.z * pw   + w3 * xv.x;
            o.y = wv.x * pz   + wv.y * pw   + wv.z * xv.x + w3 * xv.y;
            o.z = wv.x * pw   + wv.y * xv.x + wv.z * xv.y + w3 * xv.z;
            o.w = wv.x * xv.x + wv.y * xv.y + wv.z * xv.z + w3 * xv.w;
        } else {
            // window x[tbase-3 .. tbase+3] in registers, constant-indexed
            const float wn[7] = {py, pz, pw, xv.x, xv.y, xv.z, xv.w};
            const float wk[4] = {wv.x, wv.y, wv.z, w3};
            float tmp[4];
            #pragma unroll
            for (int i = 0; i < 4; i++) {
                const int t = tbase + i;
                int seg = 0;
                #pragma unroll
                for (int s = 1; s < BATCH; s++) seg += (qs[s] <= t) ? 1 : 0;
                const int  p        = t - __ldg(&qsl[seg]);
                const int  slot     = __ldg(&cidx[seg]);
                const bool valid    = (slot != pad);
                const bool use_init = valid && (__ldg(&imode[seg]) != 0);
                const float* st = cs + ((size_t)(valid ? slot : 0) * DIM + d) * SLEN;

                float acc = 0.f;
                #pragma unroll
                for (int k = 0; k < WIDTH; k++) {
                    const int delay = WIDTH - 1 - k;   // 3..0
                    const int q = p - delay;
                    float v;
                    if (q >= 0) v = wn[3 + i - delay];   // compile-time index
                    else        v = use_init ? st[SLEN + q] : 0.f;
                    acc += wk[k] * v;
                }
                tmp[i] = acc;
            }
            o = make_float4(tmp[0], tmp[1], tmp[2], tmp[3]);
        }
        __stcs(&out4row[t0 / 4 + ti], o);
    }
}

extern "C" void kernel_launch(void* const* d_in, const int* in_sizes, int n_in,
                              void* d_out, int out_size)
{
    const float* x     = (const float*)d_in[0];
    const float* w     = (const float*)d_in[1];
    const float* cs    = (const float*)d_in[2];
    const int*   qsl   = (const int*)d_in[3];
    const int*   cidx  = (const int*)d_in[4];
    const int*   imode = (const int*)d_in[5];
    const int*   ppad  = (const int*)d_in[6];
    const int*   pres  = (const int*)d_in[7];

    float* out    = (float*)d_out;
    float* out_cs = out + (size_t)DIM * TOTAL;

    fused_kernel<<<NBLK_CS + NBLK_CONV, TPB>>>(x, w, cs, qsl, cidx, imode,
                                               ppad, pres, out, out_cs);
}